// round 14
// baseline (speedup 1.0000x reference)
#include <cuda_runtime.h>
#include <cuda_fp16.h>
#include <math.h>
#include <stdint.h>

// Problem: s=4096, b=8, D=1280, H=16, DH=80, W=64, nw=64
// QKV GEMM : M=32768, N=3840, K=1280  (NT, both K-major) -> fp16 out
// ATTN     : 32768 independent 16x16x80 attention problems (fp16 in/out)
// PROJ GEMM: M=8192,  N=1280, K=5120  (NT) -> f32 out
#define CTA_N 128
#define BK 64
#define STAGES 3
#define ATTN_GRID 888            // 148 SMs * 6 resident blocks

// Scratch (device globals; no runtime allocation allowed)
__device__ __half g_xh[41943040ull];     // x as fp16
__device__ __half g_qkvwh[4915200ull];   // qkv_w as fp16
__device__ __half g_projwh[6553600ull];  // proj_w as fp16
__device__ __half g_qkvh[125829120ull];  // qkv output (fp16, attn input)
__device__ __half g_attnh[41943040ull];  // attn output, rearranged, fp16

__device__ __forceinline__ void cp16(uint32_t smem_dst, const void* gptr) {
    asm volatile("cp.async.cg.shared.global [%0], [%1], 16;"
                 :: "r"(smem_dst), "l"(gptr) : "memory");
}
#define LDSM4(d, addr)                                                         \
    asm volatile("ldmatrix.sync.aligned.m8n8.x4.shared.b16 {%0,%1,%2,%3}, [%4];" \
                 : "=r"((d)[0]), "=r"((d)[1]), "=r"((d)[2]), "=r"((d)[3])      \
                 : "r"(addr))

// ---------------------------------------------------------------------------
// f32 -> fp16 elementwise convert of 3 arrays in one launch (8 elems/thread)
// ---------------------------------------------------------------------------
__global__ void f2h3_kernel(const float* __restrict__ a, __half* __restrict__ ah, int na,
                            const float* __restrict__ b, __half* __restrict__ bh, int nb,
                            const float* __restrict__ c, __half* __restrict__ ch, int nc)
{
    int i = blockIdx.x * blockDim.x + threadIdx.x;   // 8-elem chunk id
    const int ca = na >> 3, cb = nb >> 3, cc = nc >> 3;
    const float* in;
    __half* out;
    int off;
    if (i < ca)                { in = a; out = ah; off = i; }
    else if (i < ca + cb)      { in = b; out = bh; off = i - ca; }
    else if (i < ca + cb + cc) { in = c; out = ch; off = i - ca - cb; }
    else return;
    const int e = off * 8;
    float4 v0 = *(const float4*)(in + e);
    float4 v1 = *(const float4*)(in + e + 4);
    __half2 h[4];
    h[0] = __floats2half2_rn(v0.x, v0.y);
    h[1] = __floats2half2_rn(v0.z, v0.w);
    h[2] = __floats2half2_rn(v1.x, v1.y);
    h[3] = __floats2half2_rn(v1.z, v1.w);
    *(uint4*)(out + e) = *(uint4*)h;
}

// ---------------------------------------------------------------------------
// C[M,N] = A[M,K] * B[N,K]^T + bias[N], fp16 mma m16n8k16, fp32 accumulate.
// CTA (MF*32) x 128, 8 warps (2x4), warp tile (MF*16) x 32, BK=64,
// 3-stage cp.async, XOR-swizzled fp16 tiles, ldmatrix.x4 fragments.
// MF=4 (128x128 tile) for both GEMMs -- MF=2 measured slower (R12).
// ---------------------------------------------------------------------------
template <int MF, typename OT>
__global__ __launch_bounds__(256, 2) void hgemm_nt_bias(
    const __half* __restrict__ A, const __half* __restrict__ B,
    const float* __restrict__ bias, OT* __restrict__ C,
    int M, int N, int K)
{
    constexpr int CM = MF * 32;                 // CTA rows
    constexpr int AB = CM * 128;                // A bytes per stage
    constexpr int SB = AB + 16384;              // stage bytes (B = 128*128)

    extern __shared__ __align__(16) char smc[];   // STAGES * SB
    const uint32_t sbase = (uint32_t)__cvta_generic_to_shared(smc);

    const int tid  = threadIdx.x;
    const int wid  = tid >> 5;
    const int lane = tid & 31;
    const int grp  = lane >> 2;      // 0..7
    const int qid  = lane & 3;       // 0..3

    const int wm = (wid & 1) * (MF * 16);   // warp rows
    const int wn = (wid >> 1) * 32;         // warp cols

    const __half* Ab = A + (size_t)blockIdx.y * CM * K;
    const __half* Bb = B + (size_t)blockIdx.x * CTA_N * K;

    // staging decode: thread -> (row sr + 32p, 16B-unit su)
    const int su = tid & 7;
    const int sr = tid >> 3;         // 0..31

    // ldmatrix per-thread row/unit decode
    const int a_r = (lane & 7) + ((lane >> 3) & 1) * 8;  // A: m0,m1=rows, m2,m3=+unit
    const int a_u = lane >> 4;
    const int b_r = (lane & 7) + ((lane >> 4) & 1) * 8;  // B: m0,m1=units, m2,m3=+rows
    const int b_u = (lane >> 3) & 1;

    float acc[MF][4][4];
#pragma unroll
    for (int i = 0; i < MF; i++)
#pragma unroll
        for (int j = 0; j < 4; j++)
#pragma unroll
            for (int c = 0; c < 4; c++) acc[i][j][c] = 0.f;

    const int nk = K / BK;

#define ISSUE_STAGE(kt_)                                                       \
    do {                                                                       \
        const uint32_t sb = sbase + ((kt_) % STAGES) * SB;                     \
        const int k0 = (kt_) * BK;                                             \
        _Pragma("unroll") for (int p = 0; p < CM / 32; p++) {                  \
            const int r = sr + p * 32;                                         \
            const uint32_t sw = (uint32_t)(r * 128 + ((su ^ (r & 7)) << 4));   \
            cp16(sb + sw, Ab + (size_t)r * K + k0 + su * 8);                   \
        }                                                                      \
        _Pragma("unroll") for (int p = 0; p < 4; p++) {                        \
            const int r = sr + p * 32;                                         \
            const uint32_t sw = (uint32_t)(r * 128 + ((su ^ (r & 7)) << 4));   \
            cp16(sb + AB + sw, Bb + (size_t)r * K + k0 + su * 8);              \
        }                                                                      \
        asm volatile("cp.async.commit_group;" ::: "memory");                   \
    } while (0)

    ISSUE_STAGE(0);
    ISSUE_STAGE(1);

    for (int kt = 0; kt < nk; kt++) {
        if (kt + 2 < nk) asm volatile("cp.async.wait_group 1;" ::: "memory");
        else             asm volatile("cp.async.wait_group 0;" ::: "memory");
        __syncthreads();
        if (kt + 2 < nk) ISSUE_STAGE(kt + 2);

        const uint32_t abase = sbase + (kt % STAGES) * SB;
        const uint32_t bbase = abase + AB;

#pragma unroll
        for (int kk = 0; kk < 4; kk++) {
            uint32_t a[MF][4], b[2][4];
#pragma unroll
            for (int mf = 0; mf < MF; mf++) {
                const int r = wm + mf * 16 + a_r;
                const int u = kk * 2 + a_u;
                LDSM4(a[mf], abase + r * 128 + ((u ^ (r & 7)) << 4));
            }
#pragma unroll
            for (int nfp = 0; nfp < 2; nfp++) {
                const int r = wn + nfp * 16 + b_r;
                const int u = kk * 2 + b_u;
                LDSM4(b[nfp], bbase + r * 128 + ((u ^ (r & 7)) << 4));
            }
#pragma unroll
            for (int mf = 0; mf < MF; mf++)
#pragma unroll
                for (int nf = 0; nf < 4; nf++) {
                    asm volatile(
                        "mma.sync.aligned.m16n8k16.row.col.f32.f16.f16.f32 "
                        "{%0,%1,%2,%3}, {%4,%5,%6,%7}, {%8,%9}, {%0,%1,%2,%3};"
                        : "+f"(acc[mf][nf][0]), "+f"(acc[mf][nf][1]),
                          "+f"(acc[mf][nf][2]), "+f"(acc[mf][nf][3])
                        : "r"(a[mf][0]), "r"(a[mf][1]),
                          "r"(a[mf][2]), "r"(a[mf][3]),
                          "r"(b[nf >> 1][(nf & 1) * 2]),
                          "r"(b[nf >> 1][(nf & 1) * 2 + 1]));
                }
        }
    }

    // epilogue: bias + stores (f32 -> float2, fp16 -> half2)
#pragma unroll
    for (int mf = 0; mf < MF; mf++) {
        const int row0 = blockIdx.y * CM + wm + mf * 16 + grp;
#pragma unroll
        for (int nf = 0; nf < 4; nf++) {
            const int col = blockIdx.x * CTA_N + wn + nf * 8 + qid * 2;
            const float bv0 = bias[col], bv1 = bias[col + 1];
            float o00 = acc[mf][nf][0] + bv0, o01 = acc[mf][nf][1] + bv1;
            float o10 = acc[mf][nf][2] + bv0, o11 = acc[mf][nf][3] + bv1;
            if constexpr (sizeof(OT) == 2) {
                *(__half2*)((__half*)C + (size_t)row0 * N + col) =
                    __floats2half2_rn(o00, o01);
                *(__half2*)((__half*)C + (size_t)(row0 + 8) * N + col) =
                    __floats2half2_rn(o10, o11);
            } else {
                *(float2*)((float*)C + (size_t)row0 * N + col) =
                    make_float2(o00, o01);
                *(float2*)((float*)C + (size_t)(row0 + 8) * N + col) =
                    make_float2(o10, o11);
            }
        }
    }
#undef ISSUE_STAGE
}

// ---------------------------------------------------------------------------
// Windowed attention, persistent grid-stride with double-buffered cp.async
// prefetch.  Each of ATTN_GRID blocks loops over problems r = bid + k*G;
// while computing problem r from smem, the raw fp16 qkv row of r+G streams
// into the other buffer.  Compute mapping identical to the R11 winner.
// ---------------------------------------------------------------------------
__global__ __launch_bounds__(256) void attn_kernel(const __half* __restrict__ qkv,
                                                   __half* __restrict__ O2)
{
    __shared__ __align__(16) __half raw[2][3840];   // 2 x 7680 B raw qkv rows
    __shared__ float qs[16 * 84];   // stride 84 breaks bank conflicts
    __shared__ float ks[16 * 84];
    __shared__ float vs[16 * 84];
    __shared__ float sc[16][17];

    const int tid = threadIdx.x;
    const uint32_t rawb = (uint32_t)__cvta_generic_to_shared(raw);
    const int G = ATTN_GRID;

#define PREFETCH(r_, buf_)                                                     \
    do {                                                                       \
        const char* src = (const char*)(qkv + (size_t)(r_) * 3840);            \
        const uint32_t dst = rawb + (buf_) * 7680;                             \
        _Pragma("unroll") for (int c_ = 0; c_ < 2; c_++) {                     \
            const int ch = tid + c_ * 256;                                     \
            if (ch < 480) cp16(dst + ch * 16, src + ch * 16);                  \
        }                                                                      \
        asm volatile("cp.async.commit_group;" ::: "memory");                   \
    } while (0)

    const int r0 = blockIdx.x;
    PREFETCH(r0, 0);
    if (r0 + G < 32768) PREFETCH(r0 + G, 1);

    int it = 0;
    for (int r = r0; r < 32768; r += G, it++) {
        if (r + G < 32768) asm volatile("cp.async.wait_group 1;" ::: "memory");
        else               asm volatile("cp.async.wait_group 0;" ::: "memory");
        __syncthreads();

        // convert raw fp16 (smem) -> padded f32 smem
        const __half2* row2 = (const __half2*)raw[it & 1];
#pragma unroll
        for (int c = 0; c < 3; c++) {
            int i = tid + c * 256;
            if (i < 640) {
                int h = i / 40, d = (i % 40) * 2;
                float2 q = __half22float2(row2[i]);
                float2 k = __half22float2(row2[640 + i]);
                float2 v = __half22float2(row2[1280 + i]);
                qs[h * 84 + d] = q.x; qs[h * 84 + d + 1] = q.y;
                ks[h * 84 + d] = k.x; ks[h * 84 + d + 1] = k.y;
                vs[h * 84 + d] = v.x; vs[h * 84 + d + 1] = v.y;
            }
        }
        __syncthreads();   // raw[it&1] fully consumed; safe to refill below

        if (r + 2 * G < 32768) PREFETCH(r + 2 * G, it & 1);

        // scores (4 independent chains) + warp-shuffle softmax over g=lane&15
        {
            const int h = tid >> 4, g = tid & 15;
            const float* qh = qs + h * 84;
            const float* kg = ks + g * 84;
            float s0 = 0.f, s1 = 0.f, s2 = 0.f, s3 = 0.f;
#pragma unroll
            for (int d = 0; d < 80; d += 4) {
                s0 = fmaf(qh[d],     kg[d],     s0);
                s1 = fmaf(qh[d + 1], kg[d + 1], s1);
                s2 = fmaf(qh[d + 2], kg[d + 2], s2);
                s3 = fmaf(qh[d + 3], kg[d + 3], s3);
            }
            float s = ((s0 + s1) + (s2 + s3)) * 0.11180339887498948f;
            float m = s;
#pragma unroll
            for (int o = 8; o; o >>= 1)
                m = fmaxf(m, __shfl_xor_sync(0xffffffffu, m, o));
            float e = expf(s - m);
            float sum = e;
#pragma unroll
            for (int o = 8; o; o >>= 1)
                sum += __shfl_xor_sync(0xffffffffu, sum, o);
            sc[h][g] = e / sum;
        }
        __syncthreads();

        // PV: thread (h, dl) handles d = 2*dl + 32j; float2 LDS, half2 STG
        {
            const int b    = r & 7;
            const int sidx = r >> 3;
            const int w    = sidx & 63;
            const int n    = sidx >> 6;
            const int h = tid >> 4, dl = tid & 15;
            float p[16];
#pragma unroll
            for (int g = 0; g < 16; g++) p[g] = sc[h][g];
            __half* orow =
                O2 + ((size_t)(n * 16 + h) * 8 + b) * 5120 + (size_t)w * 80;
#pragma unroll
            for (int j = 0; j < 3; j++) {
                if (j == 2 && dl >= 8) break;
                const int dbase = 2 * dl + 32 * j;
                const float* vcol = vs + dbase;
                float o0a = 0.f, o0b = 0.f, o1a = 0.f, o1b = 0.f;
#pragma unroll
                for (int g = 0; g < 16; g += 2) {
                    float2 va = *(const float2*)(vcol + g * 84);
                    float2 vb = *(const float2*)(vcol + (g + 1) * 84);
                    o0a = fmaf(p[g],     va.x, o0a);
                    o1a = fmaf(p[g],     va.y, o1a);
                    o0b = fmaf(p[g + 1], vb.x, o0b);
                    o1b = fmaf(p[g + 1], vb.y, o1b);
                }
                *(__half2*)(orow + dbase) =
                    __floats2half2_rn(o0a + o0b, o1a + o1b);
            }
        }
        __syncthreads();   // vs/sc reads done before next iter's convert
    }
#undef PREFETCH
}

// ---------------------------------------------------------------------------
// Launcher
// Inputs: 0=x (4096,8,1280) f32, 1=cu_seqlens i64 (ignored), 2=qkv_w (3840,1280),
//         3=qkv_b (3840), 4=proj_w (1280,5120), 5=proj_b (1280)
// Output: (1024, 8, 1280) f32
// ---------------------------------------------------------------------------
extern "C" void kernel_launch(void* const* d_in, const int* in_sizes, int n_in,
                              void* d_out, int out_size)
{
    const float* x      = (const float*)d_in[0];
    const float* qkv_w  = (const float*)d_in[2];
    const float* qkv_b  = (const float*)d_in[3];
    const float* proj_w = (const float*)d_in[4];
    const float* proj_b = (const float*)d_in[5];
    float* out = (float*)d_out;

    __half *xh, *qkvwh, *projwh, *qkvh, *attnh;
    cudaGetSymbolAddress((void**)&xh, g_xh);
    cudaGetSymbolAddress((void**)&qkvwh, g_qkvwh);
    cudaGetSymbolAddress((void**)&projwh, g_projwh);
    cudaGetSymbolAddress((void**)&qkvh, g_qkvh);
    cudaGetSymbolAddress((void**)&attnh, g_attnh);

    const int smem_bytes = STAGES * (128 * 128 + 16384);  // 98304
    cudaFuncSetAttribute((const void*)hgemm_nt_bias<4, __half>,
                         cudaFuncAttributeMaxDynamicSharedMemorySize, smem_bytes);
    cudaFuncSetAttribute((const void*)hgemm_nt_bias<4, float>,
                         cudaFuncAttributeMaxDynamicSharedMemorySize, smem_bytes);

    // 0) convert all three inputs to fp16 in one launch
    f2h3_kernel<<<26080, 256>>>(x, xh, 41943040,
                                qkv_w, qkvwh, 4915200,
                                proj_w, projwh, 6553600);

    // 1) QKV projection: (32768 x 1280) @ (3840 x 1280)^T + bias -> fp16
    hgemm_nt_bias<4, __half><<<dim3(3840 / CTA_N, 32768 / 128), 256, smem_bytes>>>(
        xh, qkvwh, qkv_b, qkvh, 32768, 3840, 1280);

    // 2) Windowed attention: persistent blocks, cp.async-prefetched
    attn_kernel<<<ATTN_GRID, 256>>>(qkvh, attnh);

    // 3) Output projection: (8192 x 5120) @ (1280 x 5120)^T + bias -> d_out
    hgemm_nt_bias<4, float><<<dim3(1280 / CTA_N, 8192 / 128), 256, smem_bytes>>>(
        attnh, projwh, proj_b, out, 8192, 1280, 5120);
}

// round 15
// speedup vs baseline: 1.0005x; 1.0005x over previous
#include <cuda_runtime.h>
#include <cuda_fp16.h>
#include <math.h>
#include <stdint.h>

// Problem: s=4096, b=8, D=1280, H=16, DH=80, W=64, nw=64
// QKV GEMM : M=32768, N=3840, K=1280  (NT, both K-major) -> fp16 out
// ATTN     : 32768 independent 16x16x80 attention problems (fp16 in/out)
// PROJ GEMM: M=8192,  N=1280, K=5120  (NT) -> f32 out
#define CTA_N 128
#define BK 64
#define STAGES 3
#define SST 86   // attn smem row stride (floats): banks (22g+d)%32 distinct for g=0..15

// Scratch (device globals; no runtime allocation allowed)
__device__ __half g_xh[41943040ull];     // x as fp16
__device__ __half g_qkvwh[4915200ull];   // qkv_w as fp16
__device__ __half g_projwh[6553600ull];  // proj_w as fp16
__device__ __half g_qkvh[125829120ull];  // qkv output (fp16, attn input)
__device__ __half g_attnh[41943040ull];  // attn output, rearranged, fp16

__device__ __forceinline__ void cp16(uint32_t smem_dst, const void* gptr) {
    asm volatile("cp.async.cg.shared.global [%0], [%1], 16;"
                 :: "r"(smem_dst), "l"(gptr) : "memory");
}
#define LDSM4(d, addr)                                                         \
    asm volatile("ldmatrix.sync.aligned.m8n8.x4.shared.b16 {%0,%1,%2,%3}, [%4];" \
                 : "=r"((d)[0]), "=r"((d)[1]), "=r"((d)[2]), "=r"((d)[3])      \
                 : "r"(addr))

// ---------------------------------------------------------------------------
// f32 -> fp16 elementwise convert of 3 arrays in one launch (8 elems/thread)
// ---------------------------------------------------------------------------
__global__ void f2h3_kernel(const float* __restrict__ a, __half* __restrict__ ah, int na,
                            const float* __restrict__ b, __half* __restrict__ bh, int nb,
                            const float* __restrict__ c, __half* __restrict__ ch, int nc)
{
    int i = blockIdx.x * blockDim.x + threadIdx.x;   // 8-elem chunk id
    const int ca = na >> 3, cb = nb >> 3, cc = nc >> 3;
    const float* in;
    __half* out;
    int off;
    if (i < ca)                { in = a; out = ah; off = i; }
    else if (i < ca + cb)      { in = b; out = bh; off = i - ca; }
    else if (i < ca + cb + cc) { in = c; out = ch; off = i - ca - cb; }
    else return;
    const int e = off * 8;
    float4 v0 = *(const float4*)(in + e);
    float4 v1 = *(const float4*)(in + e + 4);
    __half2 h[4];
    h[0] = __floats2half2_rn(v0.x, v0.y);
    h[1] = __floats2half2_rn(v0.z, v0.w);
    h[2] = __floats2half2_rn(v1.x, v1.y);
    h[3] = __floats2half2_rn(v1.z, v1.w);
    *(uint4*)(out + e) = *(uint4*)h;
}

// ---------------------------------------------------------------------------
// C[M,N] = A[M,K] * B[N,K]^T + bias[N], fp16 mma m16n8k16, fp32 accumulate.
// CTA (MF*32) x 128, 8 warps (2x4), warp tile (MF*16) x 32, BK=64,
// 3-stage cp.async, XOR-swizzled fp16 tiles, ldmatrix.x4 fragments.
// MF=4 (128x128 tile) for both GEMMs -- MF=2 measured slower (R12).
// ---------------------------------------------------------------------------
template <int MF, typename OT>
__global__ __launch_bounds__(256, 2) void hgemm_nt_bias(
    const __half* __restrict__ A, const __half* __restrict__ B,
    const float* __restrict__ bias, OT* __restrict__ C,
    int M, int N, int K)
{
    constexpr int CM = MF * 32;                 // CTA rows
    constexpr int AB = CM * 128;                // A bytes per stage
    constexpr int SB = AB + 16384;              // stage bytes (B = 128*128)

    extern __shared__ __align__(16) char smc[];   // STAGES * SB
    const uint32_t sbase = (uint32_t)__cvta_generic_to_shared(smc);

    const int tid  = threadIdx.x;
    const int wid  = tid >> 5;
    const int lane = tid & 31;
    const int grp  = lane >> 2;      // 0..7
    const int qid  = lane & 3;       // 0..3

    const int wm = (wid & 1) * (MF * 16);   // warp rows
    const int wn = (wid >> 1) * 32;         // warp cols

    const __half* Ab = A + (size_t)blockIdx.y * CM * K;
    const __half* Bb = B + (size_t)blockIdx.x * CTA_N * K;

    // staging decode: thread -> (row sr + 32p, 16B-unit su)
    const int su = tid & 7;
    const int sr = tid >> 3;         // 0..31

    // ldmatrix per-thread row/unit decode
    const int a_r = (lane & 7) + ((lane >> 3) & 1) * 8;  // A: m0,m1=rows, m2,m3=+unit
    const int a_u = lane >> 4;
    const int b_r = (lane & 7) + ((lane >> 4) & 1) * 8;  // B: m0,m1=units, m2,m3=+rows
    const int b_u = (lane >> 3) & 1;

    float acc[MF][4][4];
#pragma unroll
    for (int i = 0; i < MF; i++)
#pragma unroll
        for (int j = 0; j < 4; j++)
#pragma unroll
            for (int c = 0; c < 4; c++) acc[i][j][c] = 0.f;

    const int nk = K / BK;

#define ISSUE_STAGE(kt_)                                                       \
    do {                                                                       \
        const uint32_t sb = sbase + ((kt_) % STAGES) * SB;                     \
        const int k0 = (kt_) * BK;                                             \
        _Pragma("unroll") for (int p = 0; p < CM / 32; p++) {                  \
            const int r = sr + p * 32;                                         \
            const uint32_t sw = (uint32_t)(r * 128 + ((su ^ (r & 7)) << 4));   \
            cp16(sb + sw, Ab + (size_t)r * K + k0 + su * 8);                   \
        }                                                                      \
        _Pragma("unroll") for (int p = 0; p < 4; p++) {                        \
            const int r = sr + p * 32;                                         \
            const uint32_t sw = (uint32_t)(r * 128 + ((su ^ (r & 7)) << 4));   \
            cp16(sb + AB + sw, Bb + (size_t)r * K + k0 + su * 8);              \
        }                                                                      \
        asm volatile("cp.async.commit_group;" ::: "memory");                   \
    } while (0)

    ISSUE_STAGE(0);
    ISSUE_STAGE(1);

    for (int kt = 0; kt < nk; kt++) {
        if (kt + 2 < nk) asm volatile("cp.async.wait_group 1;" ::: "memory");
        else             asm volatile("cp.async.wait_group 0;" ::: "memory");
        __syncthreads();
        if (kt + 2 < nk) ISSUE_STAGE(kt + 2);

        const uint32_t abase = sbase + (kt % STAGES) * SB;
        const uint32_t bbase = abase + AB;

#pragma unroll
        for (int kk = 0; kk < 4; kk++) {
            uint32_t a[MF][4], b[2][4];
#pragma unroll
            for (int mf = 0; mf < MF; mf++) {
                const int r = wm + mf * 16 + a_r;
                const int u = kk * 2 + a_u;
                LDSM4(a[mf], abase + r * 128 + ((u ^ (r & 7)) << 4));
            }
#pragma unroll
            for (int nfp = 0; nfp < 2; nfp++) {
                const int r = wn + nfp * 16 + b_r;
                const int u = kk * 2 + b_u;
                LDSM4(b[nfp], bbase + r * 128 + ((u ^ (r & 7)) << 4));
            }
#pragma unroll
            for (int mf = 0; mf < MF; mf++)
#pragma unroll
                for (int nf = 0; nf < 4; nf++) {
                    asm volatile(
                        "mma.sync.aligned.m16n8k16.row.col.f32.f16.f16.f32 "
                        "{%0,%1,%2,%3}, {%4,%5,%6,%7}, {%8,%9}, {%0,%1,%2,%3};"
                        : "+f"(acc[mf][nf][0]), "+f"(acc[mf][nf][1]),
                          "+f"(acc[mf][nf][2]), "+f"(acc[mf][nf][3])
                        : "r"(a[mf][0]), "r"(a[mf][1]),
                          "r"(a[mf][2]), "r"(a[mf][3]),
                          "r"(b[nf >> 1][(nf & 1) * 2]),
                          "r"(b[nf >> 1][(nf & 1) * 2 + 1]));
                }
        }
    }

    // epilogue: bias + stores (f32 -> float2, fp16 -> half2)
#pragma unroll
    for (int mf = 0; mf < MF; mf++) {
        const int row0 = blockIdx.y * CM + wm + mf * 16 + grp;
#pragma unroll
        for (int nf = 0; nf < 4; nf++) {
            const int col = blockIdx.x * CTA_N + wn + nf * 8 + qid * 2;
            const float bv0 = bias[col], bv1 = bias[col + 1];
            float o00 = acc[mf][nf][0] + bv0, o01 = acc[mf][nf][1] + bv1;
            float o10 = acc[mf][nf][2] + bv0, o11 = acc[mf][nf][3] + bv1;
            if constexpr (sizeof(OT) == 2) {
                *(__half2*)((__half*)C + (size_t)row0 * N + col) =
                    __floats2half2_rn(o00, o01);
                *(__half2*)((__half*)C + (size_t)(row0 + 8) * N + col) =
                    __floats2half2_rn(o10, o11);
            } else {
                *(float2*)((float*)C + (size_t)row0 * N + col) =
                    make_float2(o00, o01);
                *(float2*)((float*)C + (size_t)(row0 + 8) * N + col) =
                    make_float2(o10, o11);
            }
        }
    }
#undef ISSUE_STAGE
}

// ---------------------------------------------------------------------------
// Windowed attention: one block per qkv row r = (n*64+w)*8 + b.
// fp16 input, f32 smem (stride 86 = conflict-free for 16-row gather),
// float2 score loads, warp-shuffle softmax, vectorized PV + half2 stores.
// ---------------------------------------------------------------------------
__global__ __launch_bounds__(256) void attn_kernel(const __half* __restrict__ qkv,
                                                   __half* __restrict__ O2)
{
    __shared__ float qs[16 * SST];
    __shared__ float ks[16 * SST];
    __shared__ float vs[16 * SST];
    __shared__ float sc[16][17];

    const int r    = blockIdx.x;
    const int b    = r & 7;
    const int sidx = r >> 3;
    const int w    = sidx & 63;
    const int n    = sidx >> 6;
    const int tid  = threadIdx.x;

    // load q,k,v: 640 half2 each, convert to f32 smem
    const __half2* row2 = (const __half2*)(qkv + (size_t)r * 3840);
#pragma unroll
    for (int it = 0; it < 3; it++) {
        int i = tid + it * 256;
        if (i < 640) {
            int h = i / 40, d = (i % 40) * 2;
            float2 q = __half22float2(row2[i]);
            float2 k = __half22float2(row2[640 + i]);
            float2 v = __half22float2(row2[1280 + i]);
            *(float2*)(qs + h * SST + d) = q;
            *(float2*)(ks + h * SST + d) = k;
            *(float2*)(vs + h * SST + d) = v;
        }
    }
    __syncthreads();

    // scores: float2 loads (conflict-free), 4 chains; shuffle softmax over g
    {
        const int h = tid >> 4, g = tid & 15;
        const float2* qh2 = (const float2*)(qs + h * SST);
        const float2* kg2 = (const float2*)(ks + g * SST);
        float s0 = 0.f, s1 = 0.f, s2 = 0.f, s3 = 0.f;
#pragma unroll
        for (int j = 0; j < 40; j += 2) {
            float2 qa = qh2[j],     ka = kg2[j];
            float2 qb = qh2[j + 1], kb = kg2[j + 1];
            s0 = fmaf(qa.x, ka.x, s0);
            s1 = fmaf(qa.y, ka.y, s1);
            s2 = fmaf(qb.x, kb.x, s2);
            s3 = fmaf(qb.y, kb.y, s3);
        }
        float s = ((s0 + s1) + (s2 + s3)) * 0.11180339887498948f;
        float m = s;
#pragma unroll
        for (int o = 8; o; o >>= 1)
            m = fmaxf(m, __shfl_xor_sync(0xffffffffu, m, o));
        float e = expf(s - m);
        float sum = e;
#pragma unroll
        for (int o = 8; o; o >>= 1)
            sum += __shfl_xor_sync(0xffffffffu, sum, o);
        sc[h][g] = e / sum;
    }
    __syncthreads();

    // PV: thread (h = tid>>4, dl = tid&15) handles d = 2*dl + 32j, j=0..2
    // (j=2 only for dl<8).  float2 LDS (lane-consecutive, conflict-free),
    // 4 independent FMA chains, half2 stores.
    {
        const int h = tid >> 4, dl = tid & 15;
        float p[16];
#pragma unroll
        for (int g = 0; g < 16; g++) p[g] = sc[h][g];
        __half* orow = O2 + ((size_t)(n * 16 + h) * 8 + b) * 5120 + (size_t)w * 80;
#pragma unroll
        for (int j = 0; j < 3; j++) {
            if (j == 2 && dl >= 8) break;
            const int dbase = 2 * dl + 32 * j;
            const float* vcol = vs + dbase;
            float o0a = 0.f, o0b = 0.f, o1a = 0.f, o1b = 0.f;
#pragma unroll
            for (int g = 0; g < 16; g += 2) {
                float2 va = *(const float2*)(vcol + g * SST);
                float2 vb = *(const float2*)(vcol + (g + 1) * SST);
                o0a = fmaf(p[g],     va.x, o0a);
                o1a = fmaf(p[g],     va.y, o1a);
                o0b = fmaf(p[g + 1], vb.x, o0b);
                o1b = fmaf(p[g + 1], vb.y, o1b);
            }
            *(__half2*)(orow + dbase) = __floats2half2_rn(o0a + o0b, o1a + o1b);
        }
    }
}

// ---------------------------------------------------------------------------
// Launcher
// Inputs: 0=x (4096,8,1280) f32, 1=cu_seqlens i64 (ignored), 2=qkv_w (3840,1280),
//         3=qkv_b (3840), 4=proj_w (1280,5120), 5=proj_b (1280)
// Output: (1024, 8, 1280) f32
// ---------------------------------------------------------------------------
extern "C" void kernel_launch(void* const* d_in, const int* in_sizes, int n_in,
                              void* d_out, int out_size)
{
    const float* x      = (const float*)d_in[0];
    const float* qkv_w  = (const float*)d_in[2];
    const float* qkv_b  = (const float*)d_in[3];
    const float* proj_w = (const float*)d_in[4];
    const float* proj_b = (const float*)d_in[5];
    float* out = (float*)d_out;

    __half *xh, *qkvwh, *projwh, *qkvh, *attnh;
    cudaGetSymbolAddress((void**)&xh, g_xh);
    cudaGetSymbolAddress((void**)&qkvwh, g_qkvwh);
    cudaGetSymbolAddress((void**)&projwh, g_projwh);
    cudaGetSymbolAddress((void**)&qkvh, g_qkvh);
    cudaGetSymbolAddress((void**)&attnh, g_attnh);

    const int smem_bytes = STAGES * (128 * 128 + 16384);  // 98304
    cudaFuncSetAttribute((const void*)hgemm_nt_bias<4, __half>,
                         cudaFuncAttributeMaxDynamicSharedMemorySize, smem_bytes);
    cudaFuncSetAttribute((const void*)hgemm_nt_bias<4, float>,
                         cudaFuncAttributeMaxDynamicSharedMemorySize, smem_bytes);

    // 0) convert all three inputs to fp16 in one launch
    f2h3_kernel<<<26080, 256>>>(x, xh, 41943040,
                                qkv_w, qkvwh, 4915200,
                                proj_w, projwh, 6553600);

    // 1) QKV projection: (32768 x 1280) @ (3840 x 1280)^T + bias -> fp16
    hgemm_nt_bias<4, __half><<<dim3(3840 / CTA_N, 32768 / 128), 256, smem_bytes>>>(
        xh, qkvwh, qkv_b, qkvh, 32768, 3840, 1280);

    // 2) Windowed attention over head axis, scatter fp16 rearranged layout
    attn_kernel<<<32768, 256>>>(qkvh, attnh);

    // 3) Output projection: (8192 x 5120) @ (1280 x 5120)^T + bias -> d_out
    hgemm_nt_bias<4, float><<<dim3(1280 / CTA_N, 8192 / 128), 256, smem_bytes>>>(
        attnh, projwh, proj_b, out, 8192, 1280, 5120);
}

// round 16
// speedup vs baseline: 1.1663x; 1.1657x over previous
#include <cuda_runtime.h>
#include <cuda_fp16.h>
#include <math.h>
#include <stdint.h>

// Problem: s=4096, b=8, D=1280, H=16, DH=80, W=64, nw=64
// QKV GEMM : M=32768, N=3840, K=1280  (NT, both K-major) -> fp16 out
// ATTN     : 32768 independent 16x16x80 problems, tensor-core, 1 warp each
// PROJ GEMM: M=8192,  N=1280, K=5120  (NT) -> f32 out
#define CTA_N 128
#define BK 64
#define STAGES 3
#define PROW 176          // attn smem row pitch (bytes) = 88 halves

// Scratch (device globals; no runtime allocation allowed)
__device__ __half g_xh[41943040ull];     // x as fp16
__device__ __half g_qkvwh[4915200ull];   // qkv_w as fp16
__device__ __half g_projwh[6553600ull];  // proj_w as fp16
__device__ __half g_qkvh[125829120ull];  // qkv output (fp16, attn input)
__device__ __half g_attnh[41943040ull];  // attn output, rearranged, fp16

__device__ __forceinline__ void cp16(uint32_t smem_dst, const void* gptr) {
    asm volatile("cp.async.cg.shared.global [%0], [%1], 16;"
                 :: "r"(smem_dst), "l"(gptr) : "memory");
}
#define LDSM4(d, addr)                                                         \
    asm volatile("ldmatrix.sync.aligned.m8n8.x4.shared.b16 {%0,%1,%2,%3}, [%4];" \
                 : "=r"((d)[0]), "=r"((d)[1]), "=r"((d)[2]), "=r"((d)[3])      \
                 : "r"(addr))
#define LDSM4T(d, addr)                                                        \
    asm volatile("ldmatrix.sync.aligned.m8n8.x4.trans.shared.b16 {%0,%1,%2,%3}, [%4];" \
                 : "=r"((d)[0]), "=r"((d)[1]), "=r"((d)[2]), "=r"((d)[3])      \
                 : "r"(addr))
#define MMA16816(acc, a0, a1, a2, a3, b0, b1)                                  \
    asm volatile("mma.sync.aligned.m16n8k16.row.col.f32.f16.f16.f32 "          \
                 "{%0,%1,%2,%3}, {%4,%5,%6,%7}, {%8,%9}, {%0,%1,%2,%3};"       \
                 : "+f"((acc)[0]), "+f"((acc)[1]), "+f"((acc)[2]), "+f"((acc)[3]) \
                 : "r"(a0), "r"(a1), "r"(a2), "r"(a3), "r"(b0), "r"(b1))

// ---------------------------------------------------------------------------
// f32 -> fp16 elementwise convert of 3 arrays in one launch (8 elems/thread)
// ---------------------------------------------------------------------------
__global__ void f2h3_kernel(const float* __restrict__ a, __half* __restrict__ ah, int na,
                            const float* __restrict__ b, __half* __restrict__ bh, int nb,
                            const float* __restrict__ c, __half* __restrict__ ch, int nc)
{
    int i = blockIdx.x * blockDim.x + threadIdx.x;   // 8-elem chunk id
    const int ca = na >> 3, cb = nb >> 3, cc = nc >> 3;
    const float* in;
    __half* out;
    int off;
    if (i < ca)                { in = a; out = ah; off = i; }
    else if (i < ca + cb)      { in = b; out = bh; off = i - ca; }
    else if (i < ca + cb + cc) { in = c; out = ch; off = i - ca - cb; }
    else return;
    const int e = off * 8;
    float4 v0 = *(const float4*)(in + e);
    float4 v1 = *(const float4*)(in + e + 4);
    __half2 h[4];
    h[0] = __floats2half2_rn(v0.x, v0.y);
    h[1] = __floats2half2_rn(v0.z, v0.w);
    h[2] = __floats2half2_rn(v1.x, v1.y);
    h[3] = __floats2half2_rn(v1.z, v1.w);
    *(uint4*)(out + e) = *(uint4*)h;
}

// ---------------------------------------------------------------------------
// C[M,N] = A[M,K] * B[N,K]^T + bias[N], fp16 mma m16n8k16, fp32 accumulate.
// CTA (MF*32) x 128, 8 warps (2x4), warp tile (MF*16) x 32, BK=64,
// 3-stage cp.async, XOR-swizzled fp16 tiles, ldmatrix.x4 fragments.
// ---------------------------------------------------------------------------
template <int MF, typename OT>
__global__ __launch_bounds__(256, 2) void hgemm_nt_bias(
    const __half* __restrict__ A, const __half* __restrict__ B,
    const float* __restrict__ bias, OT* __restrict__ C,
    int M, int N, int K)
{
    constexpr int CM = MF * 32;                 // CTA rows
    constexpr int AB = CM * 128;                // A bytes per stage
    constexpr int SB = AB + 16384;              // stage bytes (B = 128*128)

    extern __shared__ __align__(16) char smc[];   // STAGES * SB
    const uint32_t sbase = (uint32_t)__cvta_generic_to_shared(smc);

    const int tid  = threadIdx.x;
    const int wid  = tid >> 5;
    const int lane = tid & 31;
    const int grp  = lane >> 2;      // 0..7
    const int qid  = lane & 3;       // 0..3

    const int wm = (wid & 1) * (MF * 16);   // warp rows
    const int wn = (wid >> 1) * 32;         // warp cols

    const __half* Ab = A + (size_t)blockIdx.y * CM * K;
    const __half* Bb = B + (size_t)blockIdx.x * CTA_N * K;

    const int su = tid & 7;
    const int sr = tid >> 3;         // 0..31

    const int a_r = (lane & 7) + ((lane >> 3) & 1) * 8;
    const int a_u = lane >> 4;
    const int b_r = (lane & 7) + ((lane >> 4) & 1) * 8;
    const int b_u = (lane >> 3) & 1;

    float acc[MF][4][4];
#pragma unroll
    for (int i = 0; i < MF; i++)
#pragma unroll
        for (int j = 0; j < 4; j++)
#pragma unroll
            for (int c = 0; c < 4; c++) acc[i][j][c] = 0.f;

    const int nk = K / BK;

#define ISSUE_STAGE(kt_)                                                       \
    do {                                                                       \
        const uint32_t sb = sbase + ((kt_) % STAGES) * SB;                     \
        const int k0 = (kt_) * BK;                                             \
        _Pragma("unroll") for (int p = 0; p < CM / 32; p++) {                  \
            const int r = sr + p * 32;                                         \
            const uint32_t sw = (uint32_t)(r * 128 + ((su ^ (r & 7)) << 4));   \
            cp16(sb + sw, Ab + (size_t)r * K + k0 + su * 8);                   \
        }                                                                      \
        _Pragma("unroll") for (int p = 0; p < 4; p++) {                        \
            const int r = sr + p * 32;                                         \
            const uint32_t sw = (uint32_t)(r * 128 + ((su ^ (r & 7)) << 4));   \
            cp16(sb + AB + sw, Bb + (size_t)r * K + k0 + su * 8);              \
        }                                                                      \
        asm volatile("cp.async.commit_group;" ::: "memory");                   \
    } while (0)

    ISSUE_STAGE(0);
    ISSUE_STAGE(1);

    for (int kt = 0; kt < nk; kt++) {
        if (kt + 2 < nk) asm volatile("cp.async.wait_group 1;" ::: "memory");
        else             asm volatile("cp.async.wait_group 0;" ::: "memory");
        __syncthreads();
        if (kt + 2 < nk) ISSUE_STAGE(kt + 2);

        const uint32_t abase = sbase + (kt % STAGES) * SB;
        const uint32_t bbase = abase + AB;

#pragma unroll
        for (int kk = 0; kk < 4; kk++) {
            uint32_t a[MF][4], b[2][4];
#pragma unroll
            for (int mf = 0; mf < MF; mf++) {
                const int r = wm + mf * 16 + a_r;
                const int u = kk * 2 + a_u;
                LDSM4(a[mf], abase + r * 128 + ((u ^ (r & 7)) << 4));
            }
#pragma unroll
            for (int nfp = 0; nfp < 2; nfp++) {
                const int r = wn + nfp * 16 + b_r;
                const int u = kk * 2 + b_u;
                LDSM4(b[nfp], bbase + r * 128 + ((u ^ (r & 7)) << 4));
            }
#pragma unroll
            for (int mf = 0; mf < MF; mf++)
#pragma unroll
                for (int nf = 0; nf < 4; nf++) {
                    MMA16816(acc[mf][nf],
                             a[mf][0], a[mf][1], a[mf][2], a[mf][3],
                             b[nf >> 1][(nf & 1) * 2],
                             b[nf >> 1][(nf & 1) * 2 + 1]);
                }
        }
    }

    // epilogue: bias + stores (f32 -> float2, fp16 -> half2)
#pragma unroll
    for (int mf = 0; mf < MF; mf++) {
        const int row0 = blockIdx.y * CM + wm + mf * 16 + grp;
#pragma unroll
        for (int nf = 0; nf < 4; nf++) {
            const int col = blockIdx.x * CTA_N + wn + nf * 8 + qid * 2;
            const float bv0 = bias[col], bv1 = bias[col + 1];
            float o00 = acc[mf][nf][0] + bv0, o01 = acc[mf][nf][1] + bv1;
            float o10 = acc[mf][nf][2] + bv0, o11 = acc[mf][nf][3] + bv1;
            if constexpr (sizeof(OT) == 2) {
                *(__half2*)((__half*)C + (size_t)row0 * N + col) =
                    __floats2half2_rn(o00, o01);
                *(__half2*)((__half*)C + (size_t)(row0 + 8) * N + col) =
                    __floats2half2_rn(o10, o11);
            } else {
                *(float2*)((float*)C + (size_t)row0 * N + col) =
                    make_float2(o00, o01);
                *(float2*)((float*)C + (size_t)(row0 + 8) * N + col) =
                    make_float2(o10, o11);
            }
        }
    }
#undef ISSUE_STAGE
}

// ---------------------------------------------------------------------------
// Tensor-core windowed attention: one WARP per 16x16x80 problem.
// 8 warps / 8 problems per block; cooperative cp.async load into padded
// fp16 smem (rows 176B: conflict-free ldmatrix); S = Q.K^T via 10 mma;
// register softmax (shfl over qid bits); S-acc repacks directly into the
// P A-fragment; O = P.V via 5 ldmatrix.trans + 10 mma; half2 stores.
// ---------------------------------------------------------------------------
__global__ __launch_bounds__(256) void attn_kernel(const __half* __restrict__ qkv,
                                                   __half* __restrict__ O2)
{
    extern __shared__ __align__(16) char asm_[];   // 8 * 3 * 16 * 176 = 67584
    const uint32_t sbase = (uint32_t)__cvta_generic_to_shared(asm_);

    const int tid  = threadIdx.x;
    const int wid  = tid >> 5;
    const int lane = tid & 31;
    const int grp  = lane >> 2;   // 0..7
    const int qid  = lane & 3;    // 0..3
    const int r0   = blockIdx.x * 8;

    // cooperative load: 3840 16B chunks (15 per thread), padding-aware
    for (int c = tid; c < 3840; c += 256) {
        const int p   = c / 480;          // problem 0..7
        const int c4  = c - p * 480;
        const int f   = c4 / 160;         // 0=q 1=k 2=v
        const int c1  = c4 - f * 160;
        const int h   = c1 / 10;          // row 0..15
        const int dc  = c1 - h * 10;      // 16B chunk in row
        const uint32_t dst = sbase + (((p * 3 + f) * 16 + h) * PROW) + dc * 16;
        cp16(dst, qkv + (size_t)r0 * 3840 + (size_t)c * 8);
    }
    asm volatile("cp.async.commit_group;" ::: "memory");
    asm volatile("cp.async.wait_group 0;" ::: "memory");
    __syncthreads();

    const uint32_t qb = sbase + (uint32_t)(wid * 3) * 16 * PROW;
    const uint32_t kb = qb + 16 * PROW;
    const uint32_t vb = kb + 16 * PROW;

    const int a_r = (lane & 7) + ((lane >> 3) & 1) * 8;   // A / trans pattern
    const int a_u = lane >> 4;
    const int b_r = (lane & 7) + ((lane >> 4) & 1) * 8;   // B pattern
    const int b_u = (lane >> 3) & 1;

    // ---- S = Q K^T : 5 k-chunks of 16, 2 n-frags ----
    float sacc[2][4];
#pragma unroll
    for (int i = 0; i < 2; i++)
#pragma unroll
        for (int c = 0; c < 4; c++) sacc[i][c] = 0.f;

#pragma unroll
    for (int kc = 0; kc < 5; kc++) {
        uint32_t a[4], bf[4];
        LDSM4(a,  qb + a_r * PROW + kc * 32 + a_u * 16);
        LDSM4(bf, kb + b_r * PROW + kc * 32 + b_u * 16);
        MMA16816(sacc[0], a[0], a[1], a[2], a[3], bf[0], bf[1]);
        MMA16816(sacc[1], a[0], a[1], a[2], a[3], bf[2], bf[3]);
    }

    // ---- register softmax over the 16 columns ----
    // row grp   : sacc[0][0], sacc[0][1], sacc[1][0], sacc[1][1]
    // row grp+8 : sacc[0][2], sacc[0][3], sacc[1][2], sacc[1][3]
    const float scale = 0.11180339887498948f;  // 1/sqrt(80)
    float vA0 = sacc[0][0] * scale, vA1 = sacc[0][1] * scale;
    float vA2 = sacc[1][0] * scale, vA3 = sacc[1][1] * scale;
    float vB0 = sacc[0][2] * scale, vB1 = sacc[0][3] * scale;
    float vB2 = sacc[1][2] * scale, vB3 = sacc[1][3] * scale;

    float mA = fmaxf(fmaxf(vA0, vA1), fmaxf(vA2, vA3));
    float mB = fmaxf(fmaxf(vB0, vB1), fmaxf(vB2, vB3));
#pragma unroll
    for (int o = 1; o <= 2; o <<= 1) {
        mA = fmaxf(mA, __shfl_xor_sync(0xffffffffu, mA, o));
        mB = fmaxf(mB, __shfl_xor_sync(0xffffffffu, mB, o));
    }
    vA0 = expf(vA0 - mA); vA1 = expf(vA1 - mA);
    vA2 = expf(vA2 - mA); vA3 = expf(vA3 - mA);
    vB0 = expf(vB0 - mB); vB1 = expf(vB1 - mB);
    vB2 = expf(vB2 - mB); vB3 = expf(vB3 - mB);
    float sA = (vA0 + vA1) + (vA2 + vA3);
    float sB = (vB0 + vB1) + (vB2 + vB3);
#pragma unroll
    for (int o = 1; o <= 2; o <<= 1) {
        sA += __shfl_xor_sync(0xffffffffu, sA, o);
        sB += __shfl_xor_sync(0xffffffffu, sB, o);
    }
    const float iA = 1.f / sA, iB = 1.f / sB;

    // pack P into the A-fragment layout (acc layout == A layout)
    uint32_t pa0, pa1, pa2, pa3;
    *(__half2*)&pa0 = __floats2half2_rn(vA0 * iA, vA1 * iA);  // (grp,   k0-7)
    *(__half2*)&pa1 = __floats2half2_rn(vB0 * iB, vB1 * iB);  // (grp+8, k0-7)
    *(__half2*)&pa2 = __floats2half2_rn(vA2 * iA, vA3 * iA);  // (grp,   k8-15)
    *(__half2*)&pa3 = __floats2half2_rn(vB2 * iB, vB3 * iB);  // (grp+8, k8-15)

    // ---- O = P V : 5 d-chunks of 16 via ldmatrix.trans ----
    float oacc[10][4];
#pragma unroll
    for (int i = 0; i < 10; i++)
#pragma unroll
        for (int c = 0; c < 4; c++) oacc[i][c] = 0.f;

#pragma unroll
    for (int dc = 0; dc < 5; dc++) {
        uint32_t vr[4];
        LDSM4T(vr, vb + a_r * PROW + dc * 32 + a_u * 16);
        MMA16816(oacc[dc * 2],     pa0, pa1, pa2, pa3, vr[0], vr[1]);
        MMA16816(oacc[dc * 2 + 1], pa0, pa1, pa2, pa3, vr[2], vr[3]);
    }

    // ---- store to rearranged layout: row (n*16+h)*8+b, col w*80+d ----
    const int r    = r0 + wid;
    const int b    = r & 7;
    const int sidx = r >> 3;
    const int w    = sidx & 63;
    const int n    = sidx >> 6;
    __half* og0 = O2 + ((size_t)(n * 16 + grp)     * 8 + b) * 5120 + (size_t)w * 80;
    __half* og8 = O2 + ((size_t)(n * 16 + grp + 8) * 8 + b) * 5120 + (size_t)w * 80;
#pragma unroll
    for (int nf = 0; nf < 10; nf++) {
        const int d0 = nf * 8 + qid * 2;
        *(__half2*)(og0 + d0) = __floats2half2_rn(oacc[nf][0], oacc[nf][1]);
        *(__half2*)(og8 + d0) = __floats2half2_rn(oacc[nf][2], oacc[nf][3]);
    }
}

// ---------------------------------------------------------------------------
// Launcher
// Inputs: 0=x (4096,8,1280) f32, 1=cu_seqlens i64 (ignored), 2=qkv_w (3840,1280),
//         3=qkv_b (3840), 4=proj_w (1280,5120), 5=proj_b (1280)
// Output: (1024, 8, 1280) f32
// ---------------------------------------------------------------------------
extern "C" void kernel_launch(void* const* d_in, const int* in_sizes, int n_in,
                              void* d_out, int out_size)
{
    const float* x      = (const float*)d_in[0];
    const float* qkv_w  = (const float*)d_in[2];
    const float* qkv_b  = (const float*)d_in[3];
    const float* proj_w = (const float*)d_in[4];
    const float* proj_b = (const float*)d_in[5];
    float* out = (float*)d_out;

    __half *xh, *qkvwh, *projwh, *qkvh, *attnh;
    cudaGetSymbolAddress((void**)&xh, g_xh);
    cudaGetSymbolAddress((void**)&qkvwh, g_qkvwh);
    cudaGetSymbolAddress((void**)&projwh, g_projwh);
    cudaGetSymbolAddress((void**)&qkvh, g_qkvh);
    cudaGetSymbolAddress((void**)&attnh, g_attnh);

    const int smem_bytes = STAGES * (128 * 128 + 16384);  // 98304
    cudaFuncSetAttribute((const void*)hgemm_nt_bias<4, __half>,
                         cudaFuncAttributeMaxDynamicSharedMemorySize, smem_bytes);
    cudaFuncSetAttribute((const void*)hgemm_nt_bias<4, float>,
                         cudaFuncAttributeMaxDynamicSharedMemorySize, smem_bytes);
    const int attn_smem = 8 * 3 * 16 * PROW;              // 67584
    cudaFuncSetAttribute((const void*)attn_kernel,
                         cudaFuncAttributeMaxDynamicSharedMemorySize, attn_smem);

    // 0) convert all three inputs to fp16 in one launch
    f2h3_kernel<<<26080, 256>>>(x, xh, 41943040,
                                qkv_w, qkvwh, 4915200,
                                proj_w, projwh, 6553600);

    // 1) QKV projection: (32768 x 1280) @ (3840 x 1280)^T + bias -> fp16
    hgemm_nt_bias<4, __half><<<dim3(3840 / CTA_N, 32768 / 128), 256, smem_bytes>>>(
        xh, qkvwh, qkv_b, qkvh, 32768, 3840, 1280);

    // 2) Tensor-core windowed attention: 1 warp per problem, 8 per block
    attn_kernel<<<4096, 256, attn_smem>>>(qkvh, attnh);

    // 3) Output projection: (8192 x 5120) @ (1280 x 5120)^T + bias -> d_out
    hgemm_nt_bias<4, float><<<dim3(1280 / CTA_N, 8192 / 128), 256, smem_bytes>>>(
        attnh, projwh, proj_b, out, 8192, 1280, 5120);
}